// round 1
// baseline (speedup 1.0000x reference)
#include <cuda_runtime.h>
#include <math.h>

// Problem constants
#define Bc 2
#define Sc 2048
#define Dc 1024
#define Hc 16
#define DKc 64
#define Mtot (Bc * Sc)          // 4096
#define KT_STRIDE 68            // padded k-major K tile stride (floats)

// Scratch (device globals — no runtime allocation allowed)
__device__ float gQ[Bc * Hc * Sc * DKc];   // [b,h,s,dk]
__device__ float gK[Bc * Hc * Sc * DKc];
__device__ float gV[Bc * Hc * Sc * DKc];
__device__ float gA[Mtot * Dc];            // attn output, [b,s,h*dk]

// ---------------------------------------------------------------------------
// Tiled SGEMM: C[m][n] = sum_k A[m][k] * W[n][k] + bias[n]
// (torch Linear convention: y = x @ W.T + b; W is [N,K] row-major)
// Block tile 128x128, K-step 8, 256 threads, 8x8 microtile per thread.
// ---------------------------------------------------------------------------
template <bool HEAD_LAYOUT>
__device__ __forceinline__ void gemm_body(const float* __restrict__ A,
                                          const float* __restrict__ W,
                                          const float* __restrict__ bias,
                                          float* __restrict__ C) {
    __shared__ float As[8 * 132];
    __shared__ float Bs[8 * 132];

    const int tid = threadIdx.x;
    const int tx = tid & 15;
    const int ty = tid >> 4;
    const int m0 = blockIdx.y * 128;
    const int n0 = blockIdx.x * 128;

    const int lrow = tid >> 1;          // 0..127
    const int lk4 = (tid & 1) * 4;      // 0 or 4

    const float* Ap = A + (size_t)(m0 + lrow) * Dc + lk4;
    const float* Wp = W + (size_t)(n0 + lrow) * Dc + lk4;

    float acc[8][8];
#pragma unroll
    for (int i = 0; i < 8; i++)
#pragma unroll
        for (int j = 0; j < 8; j++) acc[i][j] = 0.f;

    // software-pipelined gmem load
    float4 av = *(const float4*)(Ap);
    float4 wv = *(const float4*)(Wp);

    for (int k0 = 0; k0 < Dc; k0 += 8) {
        __syncthreads();
        As[(lk4 + 0) * 132 + lrow] = av.x;
        As[(lk4 + 1) * 132 + lrow] = av.y;
        As[(lk4 + 2) * 132 + lrow] = av.z;
        As[(lk4 + 3) * 132 + lrow] = av.w;
        Bs[(lk4 + 0) * 132 + lrow] = wv.x;
        Bs[(lk4 + 1) * 132 + lrow] = wv.y;
        Bs[(lk4 + 2) * 132 + lrow] = wv.z;
        Bs[(lk4 + 3) * 132 + lrow] = wv.w;
        __syncthreads();

        if (k0 + 8 < Dc) {
            av = *(const float4*)(Ap + k0 + 8);
            wv = *(const float4*)(Wp + k0 + 8);
        }

#pragma unroll
        for (int kk = 0; kk < 8; kk++) {
            float4 a0 = *(const float4*)&As[kk * 132 + 4 * ty];
            float4 a1 = *(const float4*)&As[kk * 132 + 64 + 4 * ty];
            float4 b0 = *(const float4*)&Bs[kk * 132 + 4 * tx];
            float4 b1 = *(const float4*)&Bs[kk * 132 + 64 + 4 * tx];
            float a[8] = {a0.x, a0.y, a0.z, a0.w, a1.x, a1.y, a1.z, a1.w};
            float b[8] = {b0.x, b0.y, b0.z, b0.w, b1.x, b1.y, b1.z, b1.w};
#pragma unroll
            for (int i = 0; i < 8; i++)
#pragma unroll
                for (int j = 0; j < 8; j++)
                    acc[i][j] = fmaf(a[i], b[j], acc[i][j]);
        }
    }

#pragma unroll
    for (int i = 0; i < 8; i++) {
        const int mi = m0 + ((i < 4) ? (4 * ty + i) : (64 + 4 * ty + i - 4));
#pragma unroll
        for (int j = 0; j < 8; j++) {
            const int nj = n0 + ((j < 4) ? (4 * tx + j) : (64 + 4 * tx + j - 4));
            const float v = acc[i][j] + bias[nj];
            if (HEAD_LAYOUT) {
                // out[b, h, s, dk]
                const int bb = mi / Sc;
                const int s = mi - bb * Sc;
                const int h = nj >> 6;
                const int dk = nj & 63;
                C[(((size_t)(bb * Hc + h)) * Sc + s) * DKc + dk] = v;
            } else {
                C[(size_t)mi * Dc + nj] = v;
            }
        }
    }
}

__global__ __launch_bounds__(256) void qkv_kernel(
    const float* __restrict__ X,
    const float* __restrict__ Wq, const float* __restrict__ bq,
    const float* __restrict__ Wk, const float* __restrict__ bk,
    const float* __restrict__ Wv, const float* __restrict__ bv) {
    const float* W = Wq;
    const float* bias = bq;
    float* out = gQ;
    if (blockIdx.z == 1) { W = Wk; bias = bk; out = gK; }
    else if (blockIdx.z == 2) { W = Wv; bias = bv; out = gV; }
    gemm_body<true>(X, W, bias, out);
}

__global__ __launch_bounds__(256) void oproj_kernel(
    const float* __restrict__ Wo, const float* __restrict__ bo,
    float* __restrict__ out) {
    gemm_body<false>(gA, Wo, bo, out);
}

// ---------------------------------------------------------------------------
// Flash attention: one block per (64-row q tile, b*h). 256 threads (16x16),
// each thread owns a 4x4 score microtile and 4x4 output columns.
// ---------------------------------------------------------------------------
__global__ __launch_bounds__(256) void flash_kernel(const int* __restrict__ mask) {
    extern __shared__ float sm[];
    float* Qs = sm;                      // [64][64]   row-major (pre-scaled)
    float* Kt = Qs + 64 * 64;            // [64][68]   k-major (transposed)
    float* Vs = Kt + 64 * KT_STRIDE;     // [64][64]   row-major
    float* Ps = Vs + 64 * 64;            // [64][64]   row-major

    const int tid = threadIdx.x;
    const int tx = tid & 15;
    const int ty = tid >> 4;
    const int q0 = blockIdx.x * 64;
    const int bh = blockIdx.y;

    const float* Qg = gQ + (size_t)(bh * Sc + q0) * DKc;
    const float* Kg = gK + (size_t)bh * Sc * DKc;
    const float* Vg = gV + (size_t)bh * Sc * DKc;

    // Load Q tile, pre-scaled by 1/sqrt(dk) = 0.125
#pragma unroll
    for (int it = 0; it < 4; it++) {
        const int idx = tid + it * 256;
        const int r = idx >> 4;
        const int c4 = (idx & 15) << 2;
        float4 v = *(const float4*)(Qg + (size_t)r * DKc + c4);
        v.x *= 0.125f; v.y *= 0.125f; v.z *= 0.125f; v.w *= 0.125f;
        *(float4*)(Qs + r * 64 + c4) = v;
    }

    float m_i[4], l_i[4], o[4][4];
#pragma unroll
    for (int i = 0; i < 4; i++) {
        m_i[i] = -INFINITY;
        l_i[i] = 0.f;
#pragma unroll
        for (int j = 0; j < 4; j++) o[i][j] = 0.f;
    }

    for (int kt = 0; kt < Sc / 64; kt++) {
        const int k0 = kt * 64;
        __syncthreads();  // protect Kt/Vs/Ps from previous iteration readers
#pragma unroll
        for (int it = 0; it < 4; it++) {
            const int idx = tid + it * 256;
            const int r = idx >> 4;
            const int c4 = (idx & 15) << 2;
            float4 kv = *(const float4*)(Kg + (size_t)(k0 + r) * DKc + c4);
            Kt[(c4 + 0) * KT_STRIDE + r] = kv.x;
            Kt[(c4 + 1) * KT_STRIDE + r] = kv.y;
            Kt[(c4 + 2) * KT_STRIDE + r] = kv.z;
            Kt[(c4 + 3) * KT_STRIDE + r] = kv.w;
            float4 vv = *(const float4*)(Vg + (size_t)(k0 + r) * DKc + c4);
            *(float4*)(Vs + r * 64 + c4) = vv;
        }
        __syncthreads();

        // scores: s[i][j] = sum_k Qs[4ty+i][k] * Kt[k][4tx+j]  (already scaled)
        float s[4][4];
#pragma unroll
        for (int i = 0; i < 4; i++)
#pragma unroll
            for (int j = 0; j < 4; j++) s[i][j] = 0.f;

#pragma unroll 8
        for (int k = 0; k < 64; k++) {
            float q[4];
#pragma unroll
            for (int i = 0; i < 4; i++) q[i] = Qs[(4 * ty + i) * 64 + k];
            const float4 kb = *(const float4*)&Kt[k * KT_STRIDE + 4 * tx];
            const float b4[4] = {kb.x, kb.y, kb.z, kb.w};
#pragma unroll
            for (int i = 0; i < 4; i++)
#pragma unroll
                for (int j = 0; j < 4; j++)
                    s[i][j] = fmaf(q[i], b4[j], s[i][j]);
        }

        // mask (shape [1,1,S,S]); nonzero = keep
#pragma unroll
        for (int i = 0; i < 4; i++) {
            const int4 mk = *(const int4*)(mask + (size_t)(q0 + 4 * ty + i) * Sc + k0 + 4 * tx);
            if (mk.x == 0) s[i][0] = -1e9f;
            if (mk.y == 0) s[i][1] = -1e9f;
            if (mk.z == 0) s[i][2] = -1e9f;
            if (mk.w == 0) s[i][3] = -1e9f;
        }

        // online softmax (row groups = 16 consecutive lanes)
#pragma unroll
        for (int i = 0; i < 4; i++) {
            float mx = fmaxf(fmaxf(s[i][0], s[i][1]), fmaxf(s[i][2], s[i][3]));
#pragma unroll
            for (int off = 8; off >= 1; off >>= 1)
                mx = fmaxf(mx, __shfl_xor_sync(0xffffffffu, mx, off, 16));
            const float mnew = fmaxf(m_i[i], mx);
            const float corr = __expf(m_i[i] - mnew);
            m_i[i] = mnew;
            float rs = 0.f;
#pragma unroll
            for (int j = 0; j < 4; j++) {
                s[i][j] = __expf(s[i][j] - mnew);
                rs += s[i][j];
            }
#pragma unroll
            for (int off = 8; off >= 1; off >>= 1)
                rs += __shfl_xor_sync(0xffffffffu, rs, off, 16);
            l_i[i] = l_i[i] * corr + rs;
#pragma unroll
            for (int j = 0; j < 4; j++) o[i][j] *= corr;
        }

        // stage P in smem (conflict-free float4 writes, broadcast reads)
#pragma unroll
        for (int i = 0; i < 4; i++)
            *(float4*)&Ps[(4 * ty + i) * 64 + 4 * tx] =
                make_float4(s[i][0], s[i][1], s[i][2], s[i][3]);
        __syncthreads();

        // O += P @ V
#pragma unroll 8
        for (int k = 0; k < 64; k++) {
            float p[4];
#pragma unroll
            for (int i = 0; i < 4; i++) p[i] = Ps[(4 * ty + i) * 64 + k];
            const float4 vb = *(const float4*)&Vs[k * 64 + 4 * tx];
            const float v4[4] = {vb.x, vb.y, vb.z, vb.w};
#pragma unroll
            for (int i = 0; i < 4; i++)
#pragma unroll
                for (int j = 0; j < 4; j++)
                    o[i][j] = fmaf(p[i], v4[j], o[i][j]);
        }
    }

    // write normalized output to gA in [b, s, h*dk] layout
    const int b = bh >> 4;
    const int h = bh & 15;
#pragma unroll
    for (int i = 0; i < 4; i++) {
        const float inv = 1.f / l_i[i];
        const int row = q0 + 4 * ty + i;
        float* dst = gA + (size_t)(b * Sc + row) * Dc + h * DKc + 4 * tx;
        *(float4*)dst = make_float4(o[i][0] * inv, o[i][1] * inv,
                                    o[i][2] * inv, o[i][3] * inv);
    }
}

// ---------------------------------------------------------------------------
extern "C" void kernel_launch(void* const* d_in, const int* in_sizes, int n_in,
                              void* d_out, int out_size) {
    const float* X  = (const float*)d_in[0];
    const int* mask = (const int*)d_in[1];
    const float* Wq = (const float*)d_in[2];
    const float* bq = (const float*)d_in[3];
    const float* Wk = (const float*)d_in[4];
    const float* bk = (const float*)d_in[5];
    const float* Wv = (const float*)d_in[6];
    const float* bv = (const float*)d_in[7];
    const float* Wo = (const float*)d_in[8];
    const float* bo = (const float*)d_in[9];
    float* out = (float*)d_out;

    const int flash_smem = (64 * 64 * 3 + 64 * KT_STRIDE) * (int)sizeof(float); // 66560 B
    cudaFuncSetAttribute(flash_kernel,
                         cudaFuncAttributeMaxDynamicSharedMemorySize, flash_smem);

    dim3 gq(Dc / 128, Mtot / 128, 3);
    qkv_kernel<<<gq, 256>>>(X, Wq, bq, Wk, bk, Wv, bv);

    dim3 gf(Sc / 64, Bc * Hc);
    flash_kernel<<<gf, 256, flash_smem>>>(mask);

    dim3 go(Dc / 128, Mtot / 128);
    oproj_kernel<<<go, 256>>>(Wo, bo, out);
}